// round 14
// baseline (speedup 1.0000x reference)
#include <cuda_runtime.h>
#include <cstdint>

#define SEQ    512
#define BATCH  1024
#define NTAG   64

__device__ __forceinline__ float ex2f_(float x) {
    float y; asm("ex2.approx.ftz.f32 %0, %1;" : "=f"(y) : "f"(x)); return y;
}
__device__ __forceinline__ float lg2f_(float x) {
    float y; asm("lg2.approx.ftz.f32 %0, %1;" : "=f"(y) : "f"(x)); return y;
}
__device__ __forceinline__ unsigned long long fma2_(unsigned long long a,
                                                    unsigned long long b,
                                                    unsigned long long c) {
    unsigned long long d;
    asm("fma.rn.f32x2 %0, %1, %2, %3;" : "=l"(d) : "l"(a), "l"(b), "l"(c));
    return d;
}
__device__ __forceinline__ unsigned long long add2_(unsigned long long a,
                                                    unsigned long long b) {
    unsigned long long d;
    asm("add.rn.f32x2 %0, %1, %2;" : "=l"(d) : "l"(a), "l"(b));
    return d;
}
__device__ __forceinline__ void unpack_(unsigned long long v, float& x, float& y) {
    asm("mov.b64 {%0, %1}, %2;" : "=f"(x), "=f"(y) : "l"(v));
}
__device__ __forceinline__ unsigned long long packf_(float x, float y) {
    unsigned long long r;
    asm("mov.b64 %0, {%1, %2};" : "=l"(r) : "f"(x), "f"(y));
    return r;
}
__device__ __forceinline__ float wmax_(float v) {
#pragma unroll
    for (int d = 16; d; d >>= 1)
        v = fmaxf(v, __shfl_xor_sync(0xffffffffu, v, d));
    return v;
}
__device__ __forceinline__ int clampi_(int v, int lo, int hi) {
    return v < lo ? lo : (v > hi ? hi : v);
}

// One warp = one CTA = one batch, advancing BOTH sequence ends per iteration:
//   fwd (gather):  p_{t+1} = e^{f_t-SH} ∘ (E p_t),        t = 0 .. h-1
//   bwd (scatter): z_t     = E^T (e^{f_t-SH} ∘ z_{t+1}),  t = len-1 .. h
//   out = (C2f + C2b + lg2 <p_h, z_h>) * ln2   (exact identity, R13-validated)
// ONE pre-permuted butterfly table serves both directions:
//   fwd: S_j += E[j][j^r] * shfl_xor(p, r)         (shuffle, then multiply)
//   bwd: z_i += shfl_xor(E[j][j^r] * w_j, r)       (multiply, then shuffle)
// Two independent dependency chains per warp; 192 iterations instead of 384;
// warp count unchanged (1024, ~7 CTAs/SM, single wave). All-f32 transport.
__global__ void __launch_bounds__(32)
crf_main(const float* __restrict__ feats,
         const float* __restrict__ mask,
         const float* __restrict__ trans,
         float* __restrict__ out) {
    const int lane = threadIdx.x;
    const int b    = blockIdx.x;

    const float LN2 = 0.6931471805599453f;
    const float L2E = 1.4426950408889634f;
    const float SH2 = 6.0f * L2E;             // constant per-step down-scale

    // ---- len = sum of this batch's monotone mask column ----
    float lsum = 0.0f;
#pragma unroll
    for (int t = 0; t < 16; ++t)
        lsum += __ldcs(mask + (size_t)(t * 32 + lane) * BATCH + b);
#pragma unroll
    for (int d = 16; d; d >>= 1)
        lsum += __shfl_xor_sync(0xffffffffu, lsum, d);
    const int len  = (int)(lsum + 0.5f);
    const int h    = (len + 1) >> 1;
    const int nstF = h;
    const int nstB = len - h;
    const int lenr = (h + 3) & ~3;

    // ---- ONE pre-permuted, pre-packed table (f32x2), i = lane^r ----
    // EAC[r] = ( exp(T[lane   ][i]), exp(T[lane   ][32+i]) )
    // EBD[r] = ( exp(T[lane+32][i]), exp(T[lane+32][32+i]) )
    unsigned long long EAC[32], EBD[32];
#pragma unroll
    for (int r = 0; r < 32; ++r) {
        const int i = lane ^ r;
        EAC[r] = packf_(__expf(__ldg(trans + lane * NTAG + i)),
                        __expf(__ldg(trans + lane * NTAG + 32 + i)));
        EBD[r] = packf_(__expf(__ldg(trans + (lane + 32) * NTAG + i)),
                        __expf(__ldg(trans + (lane + 32) * NTAG + 32 + i)));
    }

    // ---- feats pipelines (fwd ascending, bwd descending) ----
    const float* fs = feats + (size_t)b * NTAG + lane;   // step s at +s*65536
    float efFL[4], efFH[4], fFL[4], fFH[4];
    float efBL[4], efBH[4], fBL[4], fBH[4];
#pragma unroll
    for (int u = 0; u < 4; ++u) {
        const float* pf0 = fs + ((size_t)u << 16);
        efFL[u] = ex2f_(fmaf(__ldcs(pf0),      L2E, -SH2));
        efFH[u] = ex2f_(fmaf(__ldcs(pf0 + 32), L2E, -SH2));
        const float* pf1 = fs + ((size_t)(u + 4) << 16);
        fFL[u] = __ldcs(pf1);
        fFH[u] = __ldcs(pf1 + 32);
        const float* pb0 = fs + ((size_t)(len - 2 - u) << 16);
        efBL[u] = ex2f_(fmaf(__ldcs(pb0),      L2E, -SH2));
        efBH[u] = ex2f_(fmaf(__ldcs(pb0 + 32), L2E, -SH2));
        const float* pb1 = fs + ((size_t)(len - 6 - u) << 16);
        fBL[u] = __ldcs(pb1);
        fBH[u] = __ldcs(pb1 + 32);
    }
    int fidxF = 8;
    int fidxB = len - 10;

    // ---- states ----
    float pF_lo = (lane == 0) ? 1.0f : 0.0f;  // fwd transported vector
    float pF_hi = 0.0f;
    float stF_lo = pF_lo, stF_hi = 0.0f;      // p_h candidate
    const float z_lo = __expf(trans[NTAG + lane]);        // z_len = exp(T[END][i])
    const float z_hi = __expf(trans[NTAG + 32 + lane]);
    float wB_lo, wB_hi;                        // bwd transported vector
    {
        const float* pl = fs + ((size_t)(len - 1) << 16);
        wB_lo = z_lo * ex2f_(fmaf(__ldcs(pl),      L2E, -SH2));
        wB_hi = z_hi * ex2f_(fmaf(__ldcs(pl + 32), L2E, -SH2));
    }
    float stB_lo = z_lo, stB_hi = z_hi;        // z_h candidate

    float C2f = 0.0f, rfF = 1.0f, lgF = 0.0f;
    float C2b = 0.0f, rfB = 1.0f, lgB = 0.0f;

#pragma unroll 1
    for (int s = 0; s < lenr; s += 4) {
#pragma unroll
        for (int u = 0; u < 4; ++u) {
            const unsigned long long z64 = 0ull;
            const unsigned long long wlo2 = packf_(wB_lo, wB_lo);
            const unsigned long long whi2 = packf_(wB_hi, wB_hi);
            unsigned long long aA0 = 0ull, aA1 = 0ull;   // fwd S_lo partials
            unsigned long long aB0 = 0ull, aB1 = 0ull;   // fwd S_hi partials
            unsigned long long zc0 = 0ull, zc1 = 0ull;   // bwd (z_lo,z_hi) partials
#pragma unroll
            for (int r = 0; r < 32; r += 2) {
                // fwd gather, round r
                {
                    const float pl = __shfl_xor_sync(0xffffffffu, pF_lo, r);
                    const float ph = __shfl_xor_sync(0xffffffffu, pF_hi, r);
                    const unsigned long long v = packf_(pl, ph);
                    aA0 = fma2_(EAC[r], v, aA0);
                    aB0 = fma2_(EBD[r], v, aB0);
                }
                // bwd scatter, round r
                {
                    const unsigned long long c =
                        fma2_(EAC[r], wlo2, fma2_(EBD[r], whi2, z64));
                    float cx, cy; unpack_(c, cx, cy);
                    const float sx = __shfl_xor_sync(0xffffffffu, cx, r);
                    const float sy = __shfl_xor_sync(0xffffffffu, cy, r);
                    zc0 = add2_(zc0, packf_(sx, sy));
                }
                // fwd gather, round r+1
                {
                    const float pl = __shfl_xor_sync(0xffffffffu, pF_lo, r + 1);
                    const float ph = __shfl_xor_sync(0xffffffffu, pF_hi, r + 1);
                    const unsigned long long v = packf_(pl, ph);
                    aA1 = fma2_(EAC[r + 1], v, aA1);
                    aB1 = fma2_(EBD[r + 1], v, aB1);
                }
                // bwd scatter, round r+1
                {
                    const unsigned long long c =
                        fma2_(EAC[r + 1], wlo2, fma2_(EBD[r + 1], whi2, z64));
                    float cx, cy; unpack_(c, cx, cy);
                    const float sx = __shfl_xor_sync(0xffffffffu, cx, r + 1);
                    const float sy = __shfl_xor_sync(0xffffffffu, cy, r + 1);
                    zc1 = add2_(zc1, packf_(sx, sy));
                }
            }

            // ---- fwd epilogue ----
            float sa0, sa1, sb0, sb1;
            unpack_(add2_(aA0, aA1), sa0, sa1);
            unpack_(add2_(aB0, aB1), sb0, sb1);
            const bool  updF = (s + u) < nstF;
            const float rrF  = (u == 2) ? rfF : 1.0f;
            const float pubF_lo = (sa0 + sa1) * rrF * efFL[u];
            const float pubF_hi = (sb0 + sb1) * rrF * efFH[u];
            stF_lo = updF ? pubF_lo : stF_lo;
            stF_hi = updF ? pubF_hi : stF_hi;
            C2f = updF ? (C2f + SH2 + ((u == 2) ? lgF : 0.0f)) : C2f;
            pF_lo = pubF_lo; pF_hi = pubF_hi;

            // ---- bwd epilogue ----
            float zl0, zh0;
            unpack_(add2_(zc0, zc1), zl0, zh0);
            const bool  updB = (s + u) < nstB;
            const float rrB  = (u == 2) ? rfB : 1.0f;
            const float SrB_lo = zl0 * rrB;
            const float SrB_hi = zh0 * rrB;
            stB_lo = updB ? SrB_lo : stB_lo;
            stB_hi = updB ? SrB_hi : stB_hi;
            C2b = updB ? (C2b + SH2 + ((u == 2) ? lgB : 0.0f)) : C2b;
            wB_lo = SrB_lo * efBL[u];
            wB_hi = SrB_hi * efBH[u];

            // ---- feats pipelines (consumed 4 iterations later) ----
            efFL[u] = ex2f_(fmaf(fFL[u], L2E, -SH2));
            efFH[u] = ex2f_(fmaf(fFH[u], L2E, -SH2));
            const float* pfF = fs + ((size_t)clampi_(fidxF, 0, SEQ - 1) << 16);
            fFL[u] = __ldcs(pfF);
            fFH[u] = __ldcs(pfF + 32);
            ++fidxF;
            efBL[u] = ex2f_(fmaf(fBL[u], L2E, -SH2));
            efBH[u] = ex2f_(fmaf(fBH[u], L2E, -SH2));
            const float* pfB = fs + ((size_t)clampi_(fidxB, 0, SEQ - 1) << 16);
            fBL[u] = __ldcs(pfB);
            fBH[u] = __ldcs(pfB + 32);
            --fidxB;

            // ---- once per 4 steps: renorms (applied next block @u==2) ----
            if (u == 3) {
                const float MF  = fmaxf(wmax_(fmaxf(pF_lo, pF_hi)), 1e-30f);
                const float lF2 = lg2f_(MF);
                rfF = ex2f_(-lF2);  lgF = lF2;
                const float MB  = fmaxf(wmax_(fmaxf(wB_lo, wB_hi)), 1e-30f);
                const float lB2 = lg2f_(MB);
                rfB = ex2f_(-lB2);  lgB = lB2;
            }
        }
    }

    // ---- combine (in-warp): out = (C2f + C2b + lg2 <p_h, z_h>) * ln2 ----
    float ss = stF_lo * stB_lo + stF_hi * stB_hi;
#pragma unroll
    for (int d = 16; d; d >>= 1)
        ss += __shfl_xor_sync(0xffffffffu, ss, d);
    if (lane == 0) out[b] = (C2f + C2b + lg2f_(ss)) * LN2;
}

extern "C" void kernel_launch(void* const* d_in, const int* in_sizes, int n_in,
                              void* d_out, int out_size) {
    const float* feats = nullptr;
    const float* maskp = nullptr;
    const float* trans = nullptr;
    for (int i = 0; i < n_in; ++i) {
        if (in_sizes[i] == SEQ * BATCH * NTAG)      feats = (const float*)d_in[i];
        else if (in_sizes[i] == SEQ * BATCH)        maskp = (const float*)d_in[i];
        else if (in_sizes[i] == NTAG * NTAG)        trans = (const float*)d_in[i];
    }
    crf_main<<<BATCH, 32>>>(feats, maskp, trans, (float*)d_out);
}